// round 15
// baseline (speedup 1.0000x reference)
#include <cuda_runtime.h>
#include <cuda_bf16.h>
#include <cuda_pipeline.h>

#define BB   2
#define NN   32
#define LL   4
#define EPSL 1e-5f
#define GRID 256
#define TPB  256

// dynamic smem layout (floats)
#define OFF_CT  0       // 5120: contraction 8x640 | final pooled4
#define OFF_FW  5120    // 8960: FFN weights 64x140 | final psum
#define OFF_SY  14080   // 8704: slabs (l>=1) | l0: h-tail W (4352) + sxu overlay
#define OFF_XA  22784   // 1024: x ping-pong 2 x 2 x 256
#define OFF_ADJ 23808   // 4352: adj+adjT (l0) | l>0: sxu overlay then h-tail W
#define DYNF    28160
#define DYNB    (DYNF*4)

// ---------------- device scratch ----------------
__device__ __align__(16) float g_hbuf[2][2048*64];
__device__ unsigned g_diag_key[LL*128];        // static zero-init; reset at run end
__device__ unsigned g_off_key [LL*128];
__device__ unsigned g_min_key4[LL] = {0xFFFFFFFFu,0xFFFFFFFFu,0xFFFFFFFFu,0xFFFFFFFFu};
__device__ int g_cnt, g_gen;

__device__ __forceinline__ unsigned fkey(float f) {
    unsigned u = __float_as_uint(f);
    return (u & 0x80000000u) ? ~u : (u | 0x80000000u);
}
__device__ __forceinline__ float funkey(unsigned k) {
    unsigned u = (k & 0x80000000u) ? (k & 0x7fffffffu) : ~k;
    return __uint_as_float(u);
}

// ---- software grid barrier ----
__device__ __forceinline__ void gsync() {
    __syncthreads();
    if (threadIdx.x == 0) {
        __threadfence();
        int g = *(volatile int*)&g_gen;
        if (atomicAdd(&g_cnt, 1) == GRID - 1) {
            g_cnt = 0;
            __threadfence();
            atomicExch(&g_gen, g + 1);
        } else {
            while (*(volatile int*)&g_gen == g) {}
        }
        __threadfence();
    }
    __syncthreads();
}

#define GBAR() asm volatile("bar.sync %0, %1;" :: "r"(barid), "r"(128) : "memory")

// ---------------- megakernel ----------------
__global__ void __launch_bounds__(TPB, 2)
mega(const int* ei, int E,
     const float* W0, const float* b0, const float* Ws, const float* bs,
     const float* ln_g, const float* ln_b,
     const float* fW0, const float* fb0, const float* fWs, const float* fbs,
     const float* fln_g, const float* fln_b,
     const float* opW, const float* opb, float* out)
{
    extern __shared__ __align__(16) float dyn[];
    __shared__ float slg[16], slb[16], sc2[16], sc1[16];
    __shared__ float sred[2][4][4], sred2[2][4][4];
    __shared__ float sfw0[64], sw0[64], sb0[64];
    __shared__ float psr[2];
    __shared__ int   sflag;

    int t   = threadIdx.x;
    int blk = blockIdx.x;
    int pair = blk >> 2;
    int b = pair >> 5, x = pair & 31;
    int y0 = (blk & 3) * 8;
    int ypar = t >> 7, tf = t & 127, wrp = tf >> 5, la = tf & 31;
    int barid = 1 + ypar;

    float* sadj  = dyn + OFF_ADJ;          // adj  (b,a,y)
    float* sadjT = dyn + OFF_ADJ + 2048;   // adjT (b,y,a)

    // ================= init: adjacency per block =================
    {
        if (t == 0) sflag = 0;
        __syncthreads();
        for (int i = t; i < 512; i += TPB)
            if (ei[2*i + 1] != 0) sflag = 1;     // int32 vs int64 detect
        for (int i = t; i < 2048; i += TPB) sadj[i] = 0.f;
        if (t < 64) { sw0[t] = W0[t]; sb0[t] = b0[t]; }
        __syncthreads();
        int stride = sflag ? 1 : 2;
        for (int e = t; e < E; e += TPB) {
            int e0 = ei[stride*e];
            int e1 = ei[stride*E + stride*e];
            int g  = e0 >> 5;
            int ls = e0 - (g << 5);
            int ld = e1 - (g << 5);
            if (g >= 0 && g < BB && ld >= 0 && ld < NN)
                atomicAdd(&sadj[(g << 10) + (ls << 5) + ld], 1.f);
        }
        __syncthreads();
        if (t < 64) { int bb = t >> 5, n = t & 31; sadj[(bb << 10) + n*33] = 2.f; }
        __syncthreads();
        for (int i = t; i < 2048; i += TPB) {
            int bb = i >> 10, aa = (i >> 5) & 31, yy = i & 31;
            sadjT[(bb << 10) + (yy << 5) + aa] = sadj[i];
        }
        if (tf < 4)
            dyn[OFF_XA + ypar*256 + tf*64] = sadj[(b << 10) + (x << 5) + y0 + 2*tf + ypar];
        __syncthreads();
    }

    // ================= layers =================
    for (int l = 0; l < LL; l++) {
        const float* hcur = g_hbuf[l & 1];
        float* bufA = dyn + OFF_SY + ypar*4352;
        float* bufB = bufA + 2176;
        float* ctw  = dyn + OFF_CT + (ypar*4 + wrp)*640;
        float* sxo  = dyn + OFF_XA + (l & 1)*512 + ypar*256;
        float* sxn  = dyn + OFF_XA + ((l + 1) & 1)*512 + ypar*256;
        float* sxup = (l == 0) ? (dyn + OFF_SY + 4352 + ypar*256)
                               : (dyn + OFF_ADJ + ypar*2176);
        int ffn_f = wrp*16 + (la >> 1);
        int half  = la & 1;

        // ---- staging (x-slab committed BEFORE FW so head wait skips FW) ----
        if (l == 0) {
            for (int i = t; i < 4096; i += TPB)
                dyn[OFF_FW + (i >> 6)*140 + 68 + (i & 63)] = fW0[(i >> 6)*65 + 1 + (i & 63)];
            if (t < 64) sfw0[t] = fW0[t*65];
            for (int i2 = t; i2 < 1024; i2 += TPB)
                __pipeline_memcpy_async(&dyn[OFF_SY + (i2 >> 4)*68 + (i2 & 15)*4],
                                        Ws + i2*4, 16);
            __pipeline_commit();
        } else {
            const float* xb = hcur + ((b*32 + x)*32)*64;
            for (int v = tf; v < 512; v += 128)
                __pipeline_memcpy_async(&bufA[(v >> 4)*68 + (v & 15)*4], xb + v*4, 16);
            __pipeline_commit();               // group: x-slab
            for (int i = t; i < 2048; i += TPB) {
                int f = i >> 5, u = i & 31;
                __pipeline_memcpy_async(&dyn[OFF_FW + f*140 + u*4 + (u >= 16 ? 4 : 0)],
                                        fWs + (l-1)*8192 + f*128 + u*4, 16);
            }
            __pipeline_commit();               // group: FW (waited later)
        }
        if (t < 16) {
            float g = ln_g[l*16 + t], bb2 = ln_b[l*16 + t];
            slg[t] = g; slb[t] = bb2; sc2[t] = g*g; sc1[t] = g*bb2;
        }
        float flg = fln_g[l*64 + ffn_f], flb = fln_b[l*64 + ffn_f];
        float fbias = (l == 0) ? fb0[ffn_f] : fbs[(l-1)*64 + ffn_f];
        if (l > 0) __pipeline_wait_prior(1);   // x-slab only; FW still streaming
        __syncthreads();

        // ---- x-side registers + folded scalar q constants (no gq array) ----
        float hxr[16];
        float A = 0.f, Bc = 0.f, rstdx, mxr;
        {
            if (l == 0) {
                float adjx = sadj[(b << 10) + (x << 5) + la];
                #pragma unroll
                for (int d = 0; d < 16; d++)
                    hxr[d] = adjx*sw0[wrp*16 + d] + sb0[wrp*16 + d];
            } else {
                #pragma unroll
                for (int j = 0; j < 4; j++) {
                    float4 v = *(const float4*)&bufA[la*68 + wrp*16 + 4*j];
                    hxr[4*j] = v.x; hxr[4*j+1] = v.y; hxr[4*j+2] = v.z; hxr[4*j+3] = v.w;
                }
            }
            float s0 = 0.f, s1 = 0.f;
            #pragma unroll
            for (int d = 0; d < 16; d++) { s0 += hxr[d]; s1 += hxr[d]*hxr[d]; }
            float mn = s0 * (1.f/16.f);
            rstdx = rsqrtf(s1*(1.f/16.f) - mn*mn + EPSL);
            mxr = mn * rstdx;
            #pragma unroll
            for (int d = 0; d < 16; d++) {
                float qx = (hxr[d] - mn)*rstdx*slg[d] + slb[d];
                A  += qx * slg[d];
                Bc += qx * slb[d];
            }
        }

        const float* hyb = hcur + b*65536;
        if (l > 0) {   // prefetch iter-0 y-slab
            int y = y0 + ypar;
            for (int v = tf; v < 512; v += 128)
                __pipeline_memcpy_async(&bufB[(v >> 4)*68 + (v & 15)*4],
                                        hyb + (v >> 4)*2048 + y*64 + (v & 15)*4, 16);
            __pipeline_commit();
        }

        // ================= y-loop: attention + contraction =================
        for (int i = 0; i < 4; i++) {
            int y = y0 + 2*i + ypar;

            float hyr[16];
            if (l == 0) {
                float adjy = sadjT[(b << 10) + (y << 5) + la];
                #pragma unroll
                for (int d = 0; d < 16; d++)
                    hyr[d] = adjy*sw0[wrp*16 + d] + sb0[wrp*16 + d];
            } else {
                __pipeline_wait_prior(0);
                GBAR();                        // slab ready; prior buffer free
                float* cur = (i & 1) ? bufA : bufB;
                #pragma unroll
                for (int j = 0; j < 4; j++) {
                    float4 v = *(const float4*)&cur[la*68 + wrp*16 + 4*j];
                    hyr[4*j] = v.x; hyr[4*j+1] = v.y; hyr[4*j+2] = v.z; hyr[4*j+3] = v.w;
                }
                if (i < 3) {
                    float* nxt = (i & 1) ? bufB : bufA;
                    int yn = y + 2;
                    for (int v = tf; v < 512; v += 128)
                        __pipeline_memcpy_async(&nxt[(v >> 4)*68 + (v & 15)*4],
                                                hyb + (v >> 4)*2048 + yn*64 + (v & 15)*4, 16);
                    __pipeline_commit();
                }
            }

            // stats: 7 accumulator chains, c2/c1 from smem broadcast
            float s0 = 0.f, s1 = 0.f, sc2p = 0.f, sc2y = 0.f, sc1y = 0.f;
            float mprod = 0.f, eprod = 0.f;
            #pragma unroll
            for (int d = 0; d < 16; d++) {
                float hy = hyr[d];
                float pr = hxr[d]*hy;
                float c2v = sc2[d], c1v = sc1[d];
                s0 += hy;
                s1 += hy*hy;
                sc2p += c2v*pr;
                sc2y += c2v*hy;
                sc1y += c1v*hy;
                mprod += pr;
                eprod += pr*pr;
            }
            float dg = rstdx*sc2p - mxr*sc2y + sc1y;
            float mny = s0 * (1.f/16.f);
            float rsy = rsqrtf(s1*(1.f/16.f) - mny*mny + EPSL);
            float s = (rsy*(dg - mny*A) + Bc) * 0.25f;
            float mm = mprod * (1.f/16.f);
            float rstd = rsqrtf(eprod*(1.f/16.f) - mm*mm + EPSL);

            // deferred-normalization softmax: unnormalized products to smem,
            // t2/t3 shuffle tree overlapped with the transpose.
            float ex = __expf(s);
            float wpr = ex * rstd;
            #pragma unroll
            for (int j = 0; j < 4; j++) {
                float4 v;
                v.x = wpr*hxr[4*j  ]*hyr[4*j  ];
                v.y = wpr*hxr[4*j+1]*hyr[4*j+1];
                v.z = wpr*hxr[4*j+2]*hyr[4*j+2];
                v.w = wpr*hxr[4*j+3]*hyr[4*j+3];
                *(float4*)&ctw[la*20 + 4*j] = v;
            }
            float t2 = ex, t3 = ex * mm * rstd;
            #pragma unroll
            for (int o = 16; o > 0; o >>= 1) {
                t2 += __shfl_xor_sync(~0u, t2, o);
                t3 += __shfl_xor_sync(~0u, t3, o);
            }
            __syncwarp();
            {
                int dd = la & 15, hh = la >> 4;
                float a0 = 0.f, a1 = 0.f, a2 = 0.f, a3 = 0.f;
                #pragma unroll
                for (int aa = 0; aa < 4; aa++) {
                    a0 += ctw[((aa     )*2 + hh)*20 + dd];
                    a1 += ctw[((aa +  4)*2 + hh)*20 + dd];
                    a2 += ctw[((aa +  8)*2 + hh)*20 + dd];
                    a3 += ctw[((aa + 12)*2 + hh)*20 + dd];
                }
                float acc = (a0 + a1) + (a2 + a3);
                acc += __shfl_xor_sync(~0u, acc, 16);
                if (la < 16) {
                    float xuv = (acc - t3) * (1.f / t2);
                    sxup[i*64 + wrp*16 + la] = slg[la]*xuv + slb[la];
                }
            }
            __syncwarp();                      // ctw safe for next iter
        } // y loop

        GBAR();                                // all sxup[*] visible to group

        // ================= batched FFN over 4 cells =================
        float acc0, acc1, acc2, acc3;
        if (l == 0 && half == 0) {
            float w0f = sfw0[ffn_f];
            acc0 = fbias + w0f*sxo[0];
            acc1 = fbias + w0f*sxo[64];
            acc2 = fbias + w0f*sxo[128];
            acc3 = fbias + w0f*sxo[192];
        } else {
            const float4* fw = (const float4*)&dyn[OFF_FW + ffn_f*140 + (half ? 68 : 0)];
            float base = half ? 0.f : fbias;
            acc0 = base; acc1 = base; acc2 = base; acc3 = base;
            const float4* x0 = (const float4*)(half ? (sxup)       : (sxo));
            const float4* x1 = (const float4*)(half ? (sxup + 64)  : (sxo + 64));
            const float4* x2 = (const float4*)(half ? (sxup + 128) : (sxo + 128));
            const float4* x3 = (const float4*)(half ? (sxup + 192) : (sxo + 192));
            #pragma unroll
            for (int j = 0; j < 16; j++) {
                float4 w = fw[j];
                float4 v0 = x0[j], v1 = x1[j], v2 = x2[j], v3 = x3[j];
                acc0 += w.x*v0.x + w.y*v0.y + w.z*v0.z + w.w*v0.w;
                acc1 += w.x*v1.x + w.y*v1.y + w.z*v1.z + w.w*v1.w;
                acc2 += w.x*v2.x + w.y*v2.y + w.z*v2.z + w.w*v2.w;
                acc3 += w.x*v3.x + w.y*v3.y + w.z*v3.z + w.w*v3.w;
            }
        }
        acc0 += __shfl_xor_sync(~0u, acc0, 1);
        acc1 += __shfl_xor_sync(~0u, acc1, 1);
        acc2 += __shfl_xor_sync(~0u, acc2, 1);
        acc3 += __shfl_xor_sync(~0u, acc3, 1);

        // LN trees for 4 cells (pipelined)
        {
            float u0 = acc0, u1 = acc1, u2 = acc2, u3 = acc3;
            float q0 = acc0*acc0, q1 = acc1*acc1, q2 = acc2*acc2, q3 = acc3*acc3;
            #pragma unroll
            for (int o = 16; o > 0; o >>= 1) {
                u0 += __shfl_xor_sync(~0u, u0, o);
                u1 += __shfl_xor_sync(~0u, u1, o);
                u2 += __shfl_xor_sync(~0u, u2, o);
                u3 += __shfl_xor_sync(~0u, u3, o);
                q0 += __shfl_xor_sync(~0u, q0, o);
                q1 += __shfl_xor_sync(~0u, q1, o);
                q2 += __shfl_xor_sync(~0u, q2, o);
                q3 += __shfl_xor_sync(~0u, q3, o);
            }
            if (la == 0) {
                sred [ypar][0][wrp] = u0; sred [ypar][1][wrp] = u1;
                sred [ypar][2][wrp] = u2; sred [ypar][3][wrp] = u3;
                sred2[ypar][0][wrp] = q0; sred2[ypar][1][wrp] = q1;
                sred2[ypar][2][wrp] = q2; sred2[ypar][3][wrp] = q3;
            }
        }
        GBAR();

        // ---- epilogue: LN + write sxn + pooling, per cell ----
        float offm = -3.0e38f, minv = 3.0e38f, dval = -3.0e38f;
        bool sawdiag = false;
        float accs[4] = {acc0, acc1, acc2, acc3};
        #pragma unroll
        for (int c = 0; c < 4; c++) {
            float mean = (sred[ypar][c][0] + sred[ypar][c][1] +
                          sred[ypar][c][2] + sred[ypar][c][3]) * (1.f/128.f);
            float ms   = (sred2[ypar][c][0] + sred2[ypar][c][1] +
                          sred2[ypar][c][2] + sred2[ypar][c][3]) * (1.f/128.f);
            float xn = (accs[c] - mean)*rsqrtf(ms - mean*mean + EPSL)*flg + flb;
            int y = y0 + 2*c + ypar;
            if (half == 0) {
                if (l < LL - 1) sxn[c*64 + ffn_f] = xn;
                minv = fminf(minv, xn);
                if (y == x) { dval = xn; sawdiag = true; }
                else offm = fmaxf(offm, xn);
            }
        }

        // ---- pooling atomics ----
        if (half == 0) {
            atomicMax(&g_off_key[l*128 + b*64 + ffn_f], fkey(offm));
            if (sawdiag) atomicMax(&g_diag_key[l*128 + b*64 + ffn_f], fkey(dval));
        }
        {
            float w = minv;
            #pragma unroll
            for (int o = 16; o > 0; o >>= 1) w = fminf(w, __shfl_xor_sync(~0u, w, o));
            if (la == 0) atomicMin(&g_min_key4[l], fkey(w));
        }

        // ---- prefetch h-tail W (l>=1) into ADJ region ----
        if (l >= 1 && l < LL - 1) {
            for (int v = tf; v < 512; v += 128) {
                int f = ypar*32 + (v >> 4), u = v & 15;
                __pipeline_memcpy_async(&dyn[OFF_ADJ + f*68 + u*4],
                                        Ws + l*4096 + f*64 + u*4, 16);
            }
            __pipeline_commit();
        }

        // ---- h-tail: next-layer h for own 8 cells ----
        if (l < LL - 1) {
            __pipeline_wait_prior(0);
            __syncthreads();
            const float* wbase = (l == 0) ? (dyn + OFF_SY) : (dyn + OFF_ADJ);
            int f = t & 63, yyA = t >> 6, yyB = yyA + 4;
            const float4* wrow = (const float4*)&wbase[f*68];
            const float4* xA = (const float4*)&dyn[OFF_XA + ((l+1)&1)*512 + (yyA & 1)*256 + (yyA >> 1)*64];
            const float4* xB = (const float4*)&dyn[OFF_XA + ((l+1)&1)*512 + (yyB & 1)*256 + (yyB >> 1)*64];
            float accA = bs[l*64 + f], accB = accA;
            #pragma unroll
            for (int j = 0; j < 16; j++) {
                float4 w = wrow[j], va = xA[j], vb = xB[j];
                accA += w.x*va.x + w.y*va.y + w.z*va.z + w.w*va.w;
                accB += w.x*vb.x + w.y*vb.y + w.z*vb.z + w.w*vb.w;
            }
            float* hn = g_hbuf[(l+1) & 1];
            hn[((b*32 + x)*32 + y0 + yyA)*64 + f] = accA;
            hn[((b*32 + x)*32 + y0 + yyB)*64 + f] = accB;
        }
        gsync();
    } // layers

    // ================= final: pool_finish all layers + BN (block 0) =================
    if (blk == 0) {
        float* pooled4 = dyn + OFF_CT;         // 4 x 256
        float* psum    = dyn + OFF_FW;         // 256
        for (int l2 = 0; l2 < LL; l2++) {
            float d0 = 0.f, d1 = 0.f, o0 = 0.f, o1 = 0.f, gmin = 0.f;
            if (t < 64) {
                d0 = funkey(g_diag_key[l2*128 + t]);
                d1 = funkey(g_diag_key[l2*128 + 64 + t]);
                o0 = funkey(g_off_key [l2*128 + t]);
                o1 = funkey(g_off_key [l2*128 + 64 + t]);
                gmin = funkey(g_min_key4[l2]);
                float m = fmaxf(d0, d1);
                #pragma unroll
                for (int o = 16; o > 0; o >>= 1) m = fmaxf(m, __shfl_xor_sync(~0u, m, o));
                if ((t & 31) == 0) psr[t >> 5] = m;
            }
            __syncthreads();
            if (t < 64) {
                float gdm = fmaxf(psr[0], psr[1]);
                float val = fabsf(gdm - gmin);
                pooled4[l2*256 + t]       = d0;
                pooled4[l2*256 + 64 + t]  = fmaxf(o0, d0 - val);
                pooled4[l2*256 + 128 + t] = d1;
                pooled4[l2*256 + 192 + t] = fmaxf(o1, d1 - val);
            }
            __syncthreads();
        }
        {
            int l2 = t >> 6, bq = (t >> 5) & 1, j = t & 31;
            const float4* w4 = (const float4*)(opW + l2*4096 + j*128);
            const float4* p4 = (const float4*)&pooled4[l2*256 + bq*128];
            float acc = opb[l2*32 + j];
            #pragma unroll
            for (int k = 0; k < 32; k++) {
                float4 w = w4[k], p = p4[k];
                acc += w.x*p.x + w.y*p.y + w.z*p.z + w.w*p.w;
            }
            psum[t] = acc;
        }
        __syncthreads();
        if (t < 32) {
            float s0 = psum[t]      + psum[64 + t] + psum[128 + t] + psum[192 + t];
            float s1 = psum[32 + t] + psum[96 + t] + psum[160 + t] + psum[224 + t];
            float m = 0.5f*(s0 + s1);
            float v = 0.5f*((s0 - m)*(s0 - m) + (s1 - m)*(s1 - m));
            float r = rsqrtf(v + EPSL);
            out[t]      = (s0 - m)*r;
            out[32 + t] = (s1 - m)*r;
        }
        // reset keys for next graph replay
        __syncthreads();
        for (int i = t; i < LL*128; i += TPB) { g_diag_key[i] = 0u; g_off_key[i] = 0u; }
        if (t < LL) g_min_key4[t] = 0xFFFFFFFFu;
    }
}

// ---------------- launch ----------------
extern "C" void kernel_launch(void* const* d_in, const int* in_sizes, int n_in,
                              void* d_out, int out_size) {
    const int*   ei    = (const int*)  d_in[0];
    const float* W0    = (const float*)d_in[2];
    const float* b0    = (const float*)d_in[3];
    const float* Ws    = (const float*)d_in[4];
    const float* bs    = (const float*)d_in[5];
    const float* ln_g  = (const float*)d_in[6];
    const float* ln_b  = (const float*)d_in[7];
    const float* fW0   = (const float*)d_in[8];
    const float* fb0   = (const float*)d_in[9];
    const float* fWs   = (const float*)d_in[10];
    const float* fbs   = (const float*)d_in[11];
    const float* fln_g = (const float*)d_in[12];
    const float* fln_b = (const float*)d_in[13];
    const float* opW   = (const float*)d_in[14];
    const float* opb   = (const float*)d_in[15];
    int E = in_sizes[0] / 2;

    cudaFuncSetAttribute(mega, cudaFuncAttributeMaxDynamicSharedMemorySize, DYNB);
    mega<<<GRID, TPB, DYNB>>>(ei, E, W0, b0, Ws, bs, ln_g, ln_b,
                              fW0, fb0, fWs, fbs, fln_g, fln_b,
                              opW, opb, (float*)d_out);
}

// round 16
// speedup vs baseline: 1.0035x; 1.0035x over previous
#include <cuda_runtime.h>
#include <cuda_bf16.h>
#include <cuda_pipeline.h>

#define BB   2
#define NN   32
#define LL   4
#define EPSL 1e-5f
#define GRID 256
#define TPB  256

// dynamic smem layout (floats)
#define OFF_CT  0       // 5120: contraction 8x640 | final pooled4
#define OFF_FW  5120    // 8960: FFN weights 64x140 | final psum
#define OFF_SY  14080   // 8704: slabs (l>=1) | l0: h-tail W (4352) + sxu overlay
#define OFF_XA  22784   // 1024: x ping-pong 2 x 2 x 256
#define OFF_ADJ 23808   // 4352: adj+adjT (l0) | l>0: sxu overlay then h-tail W
#define DYNF    28160
#define DYNB    (DYNF*4)

// ---------------- device scratch ----------------
__device__ __align__(16) float g_hbuf[2][2048*64];
__device__ unsigned g_diag_key[LL*BB*4*64];    // [l][b][x>>3][f], zero-init
__device__ unsigned g_off_key [LL*BB*4*64];
__device__ unsigned g_negmin  [LL*16];         // max of fkey(-min), zero-init
__device__ int g_cnt1[16*32];                  // leaf counters, 128B stride
__device__ int g_cnt2;
__device__ int g_gen;

__device__ __forceinline__ unsigned fkey(float f) {
    unsigned u = __float_as_uint(f);
    return (u & 0x80000000u) ? ~u : (u | 0x80000000u);
}
__device__ __forceinline__ float funkey(unsigned k) {
    unsigned u = (k & 0x80000000u) ? (k & 0x7fffffffu) : ~k;
    return __uint_as_float(u);
}

// ---- two-level tree grid barrier (16 groups x 16 blocks) ----
__device__ __forceinline__ void gsync(int blk) {
    __syncthreads();
    if (threadIdx.x == 0) {
        __threadfence();
        int g = *(volatile int*)&g_gen;
        int grp = (blk >> 4) * 32;
        if (atomicAdd(&g_cnt1[grp], 1) == 15) {
            atomicExch(&g_cnt1[grp], 0);
            if (atomicAdd(&g_cnt2, 1) == 15) {
                g_cnt2 = 0;
                __threadfence();
                atomicExch(&g_gen, g + 1);
            }
        }
        while (*(volatile int*)&g_gen == g) {}
        __threadfence();
    }
    __syncthreads();
}

#define GBAR() asm volatile("bar.sync %0, %1;" :: "r"(barid), "r"(128) : "memory")

// ---------------- megakernel ----------------
__global__ void __launch_bounds__(TPB, 2)
mega(const int* ei, int E,
     const float* W0, const float* b0, const float* Ws, const float* bs,
     const float* ln_g, const float* ln_b,
     const float* fW0, const float* fb0, const float* fWs, const float* fbs,
     const float* fln_g, const float* fln_b,
     const float* opW, const float* opb, float* out)
{
    extern __shared__ __align__(16) float dyn[];
    __shared__ float slg[16], slb[16];
    __shared__ float sred[2][4][4], sred2[2][4][4];
    __shared__ float sfw0[64], sw0[64], sb0[64];
    __shared__ int   sflag;

    int t   = threadIdx.x;
    int blk = blockIdx.x;
    int pair = blk >> 2;
    int b = pair >> 5, x = pair & 31;
    int xo = x >> 3;
    int y0 = (blk & 3) * 8;
    int ypar = t >> 7, tf = t & 127, wrp = tf >> 5, la = tf & 31;
    int barid = 1 + ypar;

    float* sadj  = dyn + OFF_ADJ;          // adj  (b,a,y)
    float* sadjT = dyn + OFF_ADJ + 2048;   // adjT (b,y,a)

    // ================= init: adjacency per block =================
    {
        if (t == 0) sflag = 0;
        __syncthreads();
        for (int i = t; i < 512; i += TPB)
            if (ei[2*i + 1] != 0) sflag = 1;     // int32 vs int64 detect
        for (int i = t; i < 2048; i += TPB) sadj[i] = 0.f;
        if (t < 64) { sw0[t] = W0[t]; sb0[t] = b0[t]; }
        __syncthreads();
        int stride = sflag ? 1 : 2;
        for (int e = t; e < E; e += TPB) {
            int e0 = ei[stride*e];
            int e1 = ei[stride*E + stride*e];
            int g  = e0 >> 5;
            int ls = e0 - (g << 5);
            int ld = e1 - (g << 5);
            if (g >= 0 && g < BB && ld >= 0 && ld < NN)
                atomicAdd(&sadj[(g << 10) + (ls << 5) + ld], 1.f);
        }
        __syncthreads();
        if (t < 64) { int bb = t >> 5, n = t & 31; sadj[(bb << 10) + n*33] = 2.f; }
        __syncthreads();
        for (int i = t; i < 2048; i += TPB) {
            int bb = i >> 10, aa = (i >> 5) & 31, yy = i & 31;
            sadjT[(bb << 10) + (yy << 5) + aa] = sadj[i];
        }
        if (tf < 4)
            dyn[OFF_XA + ypar*256 + tf*64] = sadj[(b << 10) + (x << 5) + y0 + 2*tf + ypar];
        __syncthreads();
    }

    // ================= layers =================
    for (int l = 0; l < LL; l++) {
        const float* hcur = g_hbuf[l & 1];
        float* bufA = dyn + OFF_SY + ypar*4352;
        float* bufB = bufA + 2176;
        float* ctw  = dyn + OFF_CT + (ypar*4 + wrp)*640;
        float* sxo  = dyn + OFF_XA + (l & 1)*512 + ypar*256;
        float* sxn  = dyn + OFF_XA + ((l + 1) & 1)*512 + ypar*256;
        float* sxup = (l == 0) ? (dyn + OFF_SY + 4352 + ypar*256)
                               : (dyn + OFF_ADJ + ypar*2176);
        int ffn_f = wrp*16 + (la >> 1);
        int half  = la & 1;

        // ---- staging ----
        if (l == 0) {
            for (int i = t; i < 4096; i += TPB)
                dyn[OFF_FW + (i >> 6)*140 + 68 + (i & 63)] = fW0[(i >> 6)*65 + 1 + (i & 63)];
            if (t < 64) sfw0[t] = fW0[t*65];
            for (int i2 = t; i2 < 1024; i2 += TPB)
                __pipeline_memcpy_async(&dyn[OFF_SY + (i2 >> 4)*68 + (i2 & 15)*4],
                                        Ws + i2*4, 16);
            __pipeline_commit();
        } else {
            for (int i = t; i < 2048; i += TPB) {
                int f = i >> 5, u = i & 31;
                __pipeline_memcpy_async(&dyn[OFF_FW + f*140 + u*4 + (u >= 16 ? 4 : 0)],
                                        fWs + (l-1)*8192 + f*128 + u*4, 16);
            }
            const float* xb = hcur + ((b*32 + x)*32)*64;
            for (int v = tf; v < 512; v += 128)
                __pipeline_memcpy_async(&bufA[(v >> 4)*68 + (v & 15)*4], xb + v*4, 16);
            __pipeline_commit();
        }
        if (t < 16) { slg[t] = ln_g[l*16 + t]; slb[t] = ln_b[l*16 + t]; }
        float flg = fln_g[l*64 + ffn_f], flb = fln_b[l*64 + ffn_f];
        float fbias = (l == 0) ? fb0[ffn_f] : fbs[(l-1)*64 + ffn_f];
        if (l > 0) __pipeline_wait_prior(0);
        __syncthreads();

        // ---- x-side registers + folded q constants ----
        float hxr[16], gq[16];
        float A = 0.f, Bc = 0.f;
        {
            if (l == 0) {
                float adjx = sadj[(b << 10) + (x << 5) + la];
                #pragma unroll
                for (int d = 0; d < 16; d++)
                    hxr[d] = adjx*sw0[wrp*16 + d] + sb0[wrp*16 + d];
            } else {
                #pragma unroll
                for (int j = 0; j < 4; j++) {
                    float4 v = *(const float4*)&bufA[la*68 + wrp*16 + 4*j];
                    hxr[4*j] = v.x; hxr[4*j+1] = v.y; hxr[4*j+2] = v.z; hxr[4*j+3] = v.w;
                }
            }
            float s0 = 0.f, s1 = 0.f;
            #pragma unroll
            for (int d = 0; d < 16; d++) { s0 += hxr[d]; s1 += hxr[d]*hxr[d]; }
            float mn = s0 * (1.f/16.f);
            float rstd = rsqrtf(s1*(1.f/16.f) - mn*mn + EPSL);
            #pragma unroll
            for (int d = 0; d < 16; d++) {
                float qx = (hxr[d] - mn)*rstd*slg[d] + slb[d];
                gq[d] = qx * slg[d];
                A  += gq[d];
                Bc += qx * slb[d];
            }
        }

        const float* hyb = hcur + b*65536;
        if (l > 0) {   // prefetch iter-0 y-slab
            int y = y0 + ypar;
            for (int v = tf; v < 512; v += 128)
                __pipeline_memcpy_async(&bufB[(v >> 4)*68 + (v & 15)*4],
                                        hyb + (v >> 4)*2048 + y*64 + (v & 15)*4, 16);
            __pipeline_commit();
        }

        // ================= y-loop: attention + contraction =================
        for (int i = 0; i < 4; i++) {
            int y = y0 + 2*i + ypar;

            float hyr[16];
            if (l == 0) {
                float adjy = sadjT[(b << 10) + (y << 5) + la];
                #pragma unroll
                for (int d = 0; d < 16; d++)
                    hyr[d] = adjy*sw0[wrp*16 + d] + sb0[wrp*16 + d];
            } else {
                __pipeline_wait_prior(0);
                GBAR();                        // slab ready; prior buffer free
                float* cur = (i & 1) ? bufA : bufB;
                #pragma unroll
                for (int j = 0; j < 4; j++) {
                    float4 v = *(const float4*)&cur[la*68 + wrp*16 + 4*j];
                    hyr[4*j] = v.x; hyr[4*j+1] = v.y; hyr[4*j+2] = v.z; hyr[4*j+3] = v.w;
                }
                if (i < 3) {
                    float* nxt = (i & 1) ? bufB : bufA;
                    int yn = y + 2;
                    for (int v = tf; v < 512; v += 128)
                        __pipeline_memcpy_async(&nxt[(v >> 4)*68 + (v & 15)*4],
                                                hyb + (v >> 4)*2048 + yn*64 + (v & 15)*4, 16);
                    __pipeline_commit();
                }
            }

            // stats
            float s0 = 0.f, s1 = 0.f, dg = 0.f, mprod = 0.f, eprod = 0.f;
            #pragma unroll
            for (int d = 0; d < 16; d++) {
                s0 += hyr[d];
                s1 += hyr[d]*hyr[d];
                dg += gq[d]*hyr[d];
                float pr = hxr[d]*hyr[d];
                mprod += pr;
                eprod += pr*pr;
            }
            float mny = s0 * (1.f/16.f);
            float rsy = rsqrtf(s1*(1.f/16.f) - mny*mny + EPSL);
            float s = (rsy*(dg - mny*A) + Bc) * 0.25f;
            float mm = mprod * (1.f/16.f);
            float rstd = rsqrtf(eprod*(1.f/16.f) - mm*mm + EPSL);

            // deferred-normalization softmax: unnormalized products first,
            // t2/t3 shuffle tree overlapped with the smem transpose.
            float ex = __expf(s);
            float wpr = ex * rstd;
            #pragma unroll
            for (int j = 0; j < 4; j++) {
                float4 v;
                v.x = wpr*hxr[4*j  ]*hyr[4*j  ];
                v.y = wpr*hxr[4*j+1]*hyr[4*j+1];
                v.z = wpr*hxr[4*j+2]*hyr[4*j+2];
                v.w = wpr*hxr[4*j+3]*hyr[4*j+3];
                *(float4*)&ctw[la*20 + 4*j] = v;
            }
            float t2 = ex, t3 = ex * mm * rstd;
            #pragma unroll
            for (int o = 16; o > 0; o >>= 1) {
                t2 += __shfl_xor_sync(~0u, t2, o);
                t3 += __shfl_xor_sync(~0u, t3, o);
            }
            __syncwarp();
            {
                int dd = la & 15, hh = la >> 4;
                float a0 = 0.f, a1 = 0.f, a2 = 0.f, a3 = 0.f;
                #pragma unroll
                for (int aa = 0; aa < 4; aa++) {
                    a0 += ctw[((aa     )*2 + hh)*20 + dd];
                    a1 += ctw[((aa +  4)*2 + hh)*20 + dd];
                    a2 += ctw[((aa +  8)*2 + hh)*20 + dd];
                    a3 += ctw[((aa + 12)*2 + hh)*20 + dd];
                }
                float acc = (a0 + a1) + (a2 + a3);
                acc += __shfl_xor_sync(~0u, acc, 16);
                if (la < 16) {
                    float xuv = (acc - t3) * (1.f / t2);
                    sxup[i*64 + wrp*16 + la] = slg[la]*xuv + slb[la];
                }
            }
            __syncwarp();                      // ctw safe for next iter
        } // y loop

        GBAR();                                // all sxup[*] visible to group

        // ================= batched FFN over 4 cells =================
        float acc0, acc1, acc2, acc3;
        if (l == 0 && half == 0) {
            float w0f = sfw0[ffn_f];
            acc0 = fbias + w0f*sxo[0];
            acc1 = fbias + w0f*sxo[64];
            acc2 = fbias + w0f*sxo[128];
            acc3 = fbias + w0f*sxo[192];
        } else {
            const float4* fw = (const float4*)&dyn[OFF_FW + ffn_f*140 + (half ? 68 : 0)];
            float base = half ? 0.f : fbias;
            acc0 = base; acc1 = base; acc2 = base; acc3 = base;
            const float4* x0 = (const float4*)(half ? (sxup)       : (sxo));
            const float4* x1 = (const float4*)(half ? (sxup + 64)  : (sxo + 64));
            const float4* x2 = (const float4*)(half ? (sxup + 128) : (sxo + 128));
            const float4* x3 = (const float4*)(half ? (sxup + 192) : (sxo + 192));
            #pragma unroll
            for (int j = 0; j < 16; j++) {
                float4 w = fw[j];
                float4 v0 = x0[j], v1 = x1[j], v2 = x2[j], v3 = x3[j];
                acc0 += w.x*v0.x + w.y*v0.y + w.z*v0.z + w.w*v0.w;
                acc1 += w.x*v1.x + w.y*v1.y + w.z*v1.z + w.w*v1.w;
                acc2 += w.x*v2.x + w.y*v2.y + w.z*v2.z + w.w*v2.w;
                acc3 += w.x*v3.x + w.y*v3.y + w.z*v3.z + w.w*v3.w;
            }
        }
        acc0 += __shfl_xor_sync(~0u, acc0, 1);
        acc1 += __shfl_xor_sync(~0u, acc1, 1);
        acc2 += __shfl_xor_sync(~0u, acc2, 1);
        acc3 += __shfl_xor_sync(~0u, acc3, 1);

        // LN trees for 4 cells (pipelined)
        {
            float u0 = acc0, u1 = acc1, u2 = acc2, u3 = acc3;
            float q0 = acc0*acc0, q1 = acc1*acc1, q2 = acc2*acc2, q3 = acc3*acc3;
            #pragma unroll
            for (int o = 16; o > 0; o >>= 1) {
                u0 += __shfl_xor_sync(~0u, u0, o);
                u1 += __shfl_xor_sync(~0u, u1, o);
                u2 += __shfl_xor_sync(~0u, u2, o);
                u3 += __shfl_xor_sync(~0u, u3, o);
                q0 += __shfl_xor_sync(~0u, q0, o);
                q1 += __shfl_xor_sync(~0u, q1, o);
                q2 += __shfl_xor_sync(~0u, q2, o);
                q3 += __shfl_xor_sync(~0u, q3, o);
            }
            if (la == 0) {
                sred [ypar][0][wrp] = u0; sred [ypar][1][wrp] = u1;
                sred [ypar][2][wrp] = u2; sred [ypar][3][wrp] = u3;
                sred2[ypar][0][wrp] = q0; sred2[ypar][1][wrp] = q1;
                sred2[ypar][2][wrp] = q2; sred2[ypar][3][wrp] = q3;
            }
        }
        GBAR();

        // ---- epilogue: LN + write sxn + pooling, per cell ----
        float offm = -3.0e38f, minv = 3.0e38f, dval = -3.0e38f;
        bool sawdiag = false;
        float accs[4] = {acc0, acc1, acc2, acc3};
        #pragma unroll
        for (int c = 0; c < 4; c++) {
            float mean = (sred[ypar][c][0] + sred[ypar][c][1] +
                          sred[ypar][c][2] + sred[ypar][c][3]) * (1.f/128.f);
            float ms   = (sred2[ypar][c][0] + sred2[ypar][c][1] +
                          sred2[ypar][c][2] + sred2[ypar][c][3]) * (1.f/128.f);
            float xn = (accs[c] - mean)*rsqrtf(ms - mean*mean + EPSL)*flg + flb;
            int y = y0 + 2*c + ypar;
            if (half == 0) {
                if (l < LL - 1) sxn[c*64 + ffn_f] = xn;
                minv = fminf(minv, xn);
                if (y == x) { dval = xn; sawdiag = true; }
                else offm = fmaxf(offm, xn);
            }
        }

        // ---- pooling atomics (octant-spread keys) ----
        if (half == 0) {
            int kidx = ((l*2 + b)*4 + xo)*64 + ffn_f;
            atomicMax(&g_off_key[kidx], fkey(offm));
            if (sawdiag) atomicMax(&g_diag_key[kidx], fkey(dval));
        }
        {
            float w = minv;
            #pragma unroll
            for (int o = 16; o > 0; o >>= 1) w = fminf(w, __shfl_xor_sync(~0u, w, o));
            if (la == 0) atomicMax(&g_negmin[l*16 + (blk & 15)], fkey(-w));
        }

        // ---- prefetch h-tail W (l>=1) into ADJ region ----
        if (l >= 1 && l < LL - 1) {
            for (int v = tf; v < 512; v += 128) {
                int f = ypar*32 + (v >> 4), u = v & 15;
                __pipeline_memcpy_async(&dyn[OFF_ADJ + f*68 + u*4],
                                        Ws + l*4096 + f*64 + u*4, 16);
            }
            __pipeline_commit();
        }

        // ---- h-tail: next-layer h for own 8 cells ----
        if (l < LL - 1) {
            __pipeline_wait_prior(0);
            __syncthreads();
            const float* wbase = (l == 0) ? (dyn + OFF_SY) : (dyn + OFF_ADJ);
            int f = t & 63, yyA = t >> 6, yyB = yyA + 4;
            const float4* wrow = (const float4*)&wbase[f*68];
            const float4* xA = (const float4*)&dyn[OFF_XA + ((l+1)&1)*512 + (yyA & 1)*256 + (yyA >> 1)*64];
            const float4* xB = (const float4*)&dyn[OFF_XA + ((l+1)&1)*512 + (yyB & 1)*256 + (yyB >> 1)*64];
            float accA = bs[l*64 + f], accB = accA;
            #pragma unroll
            for (int j = 0; j < 16; j++) {
                float4 w = wrow[j], va = xA[j], vb = xB[j];
                accA += w.x*va.x + w.y*va.y + w.z*va.z + w.w*va.w;
                accB += w.x*vb.x + w.y*vb.y + w.z*vb.z + w.w*vb.w;
            }
            float* hn = g_hbuf[(l+1) & 1];
            hn[((b*32 + x)*32 + y0 + yyA)*64 + f] = accA;
            hn[((b*32 + x)*32 + y0 + yyB)*64 + f] = accB;
        }
        gsync(blk);
    } // layers

    // ================= final: pool_finish all layers + BN (block 0) =================
    if (blk == 0) {
        float* pooled4 = dyn + OFF_CT;         // 4 x 256
        float* psum    = dyn + OFF_FW;         // 256
        for (int l2 = 0; l2 < LL; l2++) {
            if (t < 64) {
                unsigned dk0 = 0u, dk1 = 0u, ok0 = 0u, ok1 = 0u;
                #pragma unroll
                for (int q = 0; q < 4; q++) {
                    dk0 = max(dk0, g_diag_key[((l2*2 + 0)*4 + q)*64 + t]);
                    dk1 = max(dk1, g_diag_key[((l2*2 + 1)*4 + q)*64 + t]);
                    ok0 = max(ok0, g_off_key [((l2*2 + 0)*4 + q)*64 + t]);
                    ok1 = max(ok1, g_off_key [((l2*2 + 1)*4 + q)*64 + t]);
                }
                float d0 = funkey(dk0), d1 = funkey(dk1);
                float o0 = funkey(ok0), o1 = funkey(ok1);
                unsigned nm = 0u;
                #pragma unroll
                for (int k = 0; k < 16; k++) nm = max(nm, g_negmin[l2*16 + k]);
                float gmin = -funkey(nm);
                float m = fmaxf(d0, d1);
                #pragma unroll
                for (int o = 16; o > 0; o >>= 1) m = fmaxf(m, __shfl_xor_sync(~0u, m, o));
                m = fmaxf(m, __shfl_sync(~0u, m, 0, 32));      // warp-local max
                // combine across the two warps via smem
                __shared__ float psr2[2];
                if ((t & 31) == 0) psr2[t >> 5] = m;
                __syncwarp();
                __syncthreads();
                float gdm = fmaxf(psr2[0], psr2[1]);
                float val = fabsf(gdm - gmin);
                pooled4[l2*256 + t]       = d0;
                pooled4[l2*256 + 64 + t]  = fmaxf(o0, d0 - val);
                pooled4[l2*256 + 128 + t] = d1;
                pooled4[l2*256 + 192 + t] = fmaxf(o1, d1 - val);
            } else {
                __syncthreads();
            }
            __syncthreads();
        }
        {
            int l2 = t >> 6, bq = (t >> 5) & 1, j = t & 31;
            const float4* w4 = (const float4*)(opW + l2*4096 + j*128);
            const float4* p4 = (const float4*)&pooled4[l2*256 + bq*128];
            float acc = opb[l2*32 + j];
            #pragma unroll
            for (int k = 0; k < 32; k++) {
                float4 w = w4[k], p = p4[k];
                acc += w.x*p.x + w.y*p.y + w.z*p.z + w.w*p.w;
            }
            psum[t] = acc;
        }
        __syncthreads();
        if (t < 32) {
            float s0 = psum[t]      + psum[64 + t] + psum[128 + t] + psum[192 + t];
            float s1 = psum[32 + t] + psum[96 + t] + psum[160 + t] + psum[224 + t];
            float m = 0.5f*(s0 + s1);
            float v = 0.5f*((s0 - m)*(s0 - m) + (s1 - m)*(s1 - m));
            float r = rsqrtf(v + EPSL);
            out[t]      = (s0 - m)*r;
            out[32 + t] = (s1 - m)*r;
        }
        // reset keys for next graph replay
        __syncthreads();
        for (int i = t; i < LL*BB*4*64; i += TPB) { g_diag_key[i] = 0u; g_off_key[i] = 0u; }
        if (t < LL*16) g_negmin[t] = 0u;
    }
}

// ---------------- launch ----------------
extern "C" void kernel_launch(void* const* d_in, const int* in_sizes, int n_in,
                              void* d_out, int out_size) {
    const int*   ei    = (const int*)  d_in[0];
    const float* W0    = (const float*)d_in[2];
    const float* b0    = (const float*)d_in[3];
    const float* Ws    = (const float*)d_in[4];
    const float* bs    = (const float*)d_in[5];
    const float* ln_g  = (const float*)d_in[6];
    const float* ln_b  = (const float*)d_in[7];
    const float* fW0   = (const float*)d_in[8];
    const float* fb0   = (const float*)d_in[9];
    const float* fWs   = (const float*)d_in[10];
    const float* fbs   = (const float*)d_in[11];
    const float* fln_g = (const float*)d_in[12];
    const float* fln_b = (const float*)d_in[13];
    const float* opW   = (const float*)d_in[14];
    const float* opb   = (const float*)d_in[15];
    int E = in_sizes[0] / 2;

    cudaFuncSetAttribute(mega, cudaFuncAttributeMaxDynamicSharedMemorySize, DYNB);
    mega<<<GRID, TPB, DYNB>>>(ei, E, W0, b0, Ws, bs, ln_g, ln_b,
                              fW0, fb0, fWs, fbs, fln_g, fln_b,
                              opW, opb, (float*)d_out);
}

// round 17
// speedup vs baseline: 1.0964x; 1.0925x over previous
#include <cuda_runtime.h>
#include <cuda_bf16.h>
#include <cuda_pipeline.h>

#define BB   2
#define NN   32
#define LL   4
#define EPSL 1e-5f
#define GRID 256
#define TPB  256

// dynamic smem layout (floats)
#define OFF_CT  0       // 5120: contraction 8x640 | final pooled4
#define OFF_FW  5120    // 8960: FFN weights 64x140 | final psum
#define OFF_SY  14080   // 8704: slabs (l>=1) | l0: h-tail W (4352) + sxu overlay
#define OFF_XA  22784   // 1024: x ping-pong 2 x 2 x 256
#define OFF_ADJ 23808   // 4352: adj+adjT (l0) | l>0: sxu overlay then h-tail W
#define DYNF    28160
#define DYNB    (DYNF*4)

// ---------------- device scratch ----------------
__device__ __align__(16) float g_hbuf[2][2048*64];
__device__ unsigned g_diag_key[LL*128];        // static zero-init; reset at run end
__device__ unsigned g_off_key [LL*128];
__device__ unsigned g_min_key4[LL] = {0xFFFFFFFFu,0xFFFFFFFFu,0xFFFFFFFFu,0xFFFFFFFFu};
__device__ int g_cnt_b[2][32];                 // per-batch counters (128B apart)
__device__ int g_gen_b[2][32];
__device__ int g_fin;

__device__ __forceinline__ unsigned fkey(float f) {
    unsigned u = __float_as_uint(f);
    return (u & 0x80000000u) ? ~u : (u | 0x80000000u);
}
__device__ __forceinline__ float funkey(unsigned k) {
    unsigned u = (k & 0x80000000u) ? (k & 0x7fffffffu) : ~k;
    return __uint_as_float(u);
}

// ---- per-batch grid barrier (128 blocks each) ----
__device__ __forceinline__ void gsync_b(int b) {
    __syncthreads();
    if (threadIdx.x == 0) {
        __threadfence();
        int g = *(volatile int*)&g_gen_b[b][0];
        if (atomicAdd(&g_cnt_b[b][0], 1) == 127) {
            g_cnt_b[b][0] = 0;
            __threadfence();
            atomicExch(&g_gen_b[b][0], g + 1);
        } else {
            while (*(volatile int*)&g_gen_b[b][0] == g) {}
        }
        __threadfence();
    }
    __syncthreads();
}

#define GBAR() asm volatile("bar.sync %0, %1;" :: "r"(barid), "r"(128) : "memory")

// ---------------- megakernel ----------------
__global__ void __launch_bounds__(TPB, 2)
mega(const int* ei, int E,
     const float* W0, const float* b0, const float* Ws, const float* bs,
     const float* ln_g, const float* ln_b,
     const float* fW0, const float* fb0, const float* fWs, const float* fbs,
     const float* fln_g, const float* fln_b,
     const float* opW, const float* opb, float* out)
{
    extern __shared__ __align__(16) float dyn[];
    __shared__ float slg[16], slb[16];
    __shared__ float sred[2][4][4], sred2[2][4][4];
    __shared__ float sfw0[64], sw0[64], sb0[64];
    __shared__ float psr[2];
    __shared__ int   sflag;

    int t   = threadIdx.x;
    int blk = blockIdx.x;
    int pair = blk >> 2;
    int b = pair >> 5, x = pair & 31;
    int y0 = (blk & 3) * 8;
    int ypar = t >> 7, tf = t & 127, wrp = tf >> 5, la = tf & 31;
    int barid = 1 + ypar;

    float* sadj  = dyn + OFF_ADJ;          // adj  (b,a,y)
    float* sadjT = dyn + OFF_ADJ + 2048;   // adjT (b,y,a)

    // ================= init: adjacency per block =================
    {
        if (t == 0) sflag = 0;
        __syncthreads();
        for (int i = t; i < 512; i += TPB)
            if (ei[2*i + 1] != 0) sflag = 1;     // int32 vs int64 detect
        for (int i = t; i < 2048; i += TPB) sadj[i] = 0.f;
        if (t < 64) { sw0[t] = W0[t]; sb0[t] = b0[t]; }
        __syncthreads();
        int stride = sflag ? 1 : 2;
        for (int e = t; e < E; e += TPB) {
            int e0 = ei[stride*e];
            int e1 = ei[stride*E + stride*e];
            int g  = e0 >> 5;
            int ls = e0 - (g << 5);
            int ld = e1 - (g << 5);
            if (g >= 0 && g < BB && ld >= 0 && ld < NN)
                atomicAdd(&sadj[(g << 10) + (ls << 5) + ld], 1.f);
        }
        __syncthreads();
        if (t < 64) { int bb = t >> 5, n = t & 31; sadj[(bb << 10) + n*33] = 2.f; }
        __syncthreads();
        for (int i = t; i < 2048; i += TPB) {
            int bb = i >> 10, aa = (i >> 5) & 31, yy = i & 31;
            sadjT[(bb << 10) + (yy << 5) + aa] = sadj[i];
        }
        if (tf < 4)
            dyn[OFF_XA + ypar*256 + tf*64] = sadj[(b << 10) + (x << 5) + y0 + 2*tf + ypar];
        __syncthreads();
    }

    // ================= layers =================
    for (int l = 0; l < LL; l++) {
        const float* hcur = g_hbuf[l & 1];
        float* bufA = dyn + OFF_SY + ypar*4352;
        float* bufB = bufA + 2176;
        float* ctw  = dyn + OFF_CT + (ypar*4 + wrp)*640;
        float* sxo  = dyn + OFF_XA + (l & 1)*512 + ypar*256;
        float* sxn  = dyn + OFF_XA + ((l + 1) & 1)*512 + ypar*256;
        float* sxup = (l == 0) ? (dyn + OFF_SY + 4352 + ypar*256)
                               : (dyn + OFF_ADJ + ypar*2176);
        int ffn_f = wrp*16 + (la >> 1);
        int half  = la & 1;

        // ---- staging (FW for this layer was prefetched at end of prev layer) ----
        if (l == 0) {
            for (int i = t; i < 4096; i += TPB)
                dyn[OFF_FW + (i >> 6)*140 + 68 + (i & 63)] = fW0[(i >> 6)*65 + 1 + (i & 63)];
            if (t < 64) sfw0[t] = fW0[t*65];
            for (int i2 = t; i2 < 1024; i2 += TPB)
                __pipeline_memcpy_async(&dyn[OFF_SY + (i2 >> 4)*68 + (i2 & 15)*4],
                                        Ws + i2*4, 16);
            __pipeline_commit();
        } else {
            const float* xb = hcur + ((b*32 + x)*32)*64;
            for (int v = tf; v < 512; v += 128)
                __pipeline_memcpy_async(&bufA[(v >> 4)*68 + (v & 15)*4], xb + v*4, 16);
            __pipeline_commit();
        }
        if (t < 16) { slg[t] = ln_g[l*16 + t]; slb[t] = ln_b[l*16 + t]; }
        float flg = fln_g[l*64 + ffn_f], flb = fln_b[l*64 + ffn_f];
        float fbias = (l == 0) ? fb0[ffn_f] : fbs[(l-1)*64 + ffn_f];
        if (l > 0) __pipeline_wait_prior(0);   // x-slab only (FW done long ago)
        __syncthreads();

        // ---- x-side registers + folded q constants ----
        float hxr[16], gq[16];
        float A = 0.f, Bc = 0.f;
        {
            if (l == 0) {
                float adjx = sadj[(b << 10) + (x << 5) + la];
                #pragma unroll
                for (int d = 0; d < 16; d++)
                    hxr[d] = adjx*sw0[wrp*16 + d] + sb0[wrp*16 + d];
            } else {
                #pragma unroll
                for (int j = 0; j < 4; j++) {
                    float4 v = *(const float4*)&bufA[la*68 + wrp*16 + 4*j];
                    hxr[4*j] = v.x; hxr[4*j+1] = v.y; hxr[4*j+2] = v.z; hxr[4*j+3] = v.w;
                }
            }
            float s0 = 0.f, s1 = 0.f;
            #pragma unroll
            for (int d = 0; d < 16; d++) { s0 += hxr[d]; s1 += hxr[d]*hxr[d]; }
            float mn = s0 * (1.f/16.f);
            float rstd = rsqrtf(s1*(1.f/16.f) - mn*mn + EPSL);
            #pragma unroll
            for (int d = 0; d < 16; d++) {
                float qx = (hxr[d] - mn)*rstd*slg[d] + slb[d];
                gq[d] = qx * slg[d];
                A  += gq[d];
                Bc += qx * slb[d];
            }
        }

        const float* hyb = hcur + b*65536;
        if (l > 0) {   // prefetch iter-0 y-slab
            int y = y0 + ypar;
            for (int v = tf; v < 512; v += 128)
                __pipeline_memcpy_async(&bufB[(v >> 4)*68 + (v & 15)*4],
                                        hyb + (v >> 4)*2048 + y*64 + (v & 15)*4, 16);
            __pipeline_commit();
        }

        // ================= y-loop: attention + contraction =================
        for (int i = 0; i < 4; i++) {
            int y = y0 + 2*i + ypar;

            float hyr[16];
            if (l == 0) {
                float adjy = sadjT[(b << 10) + (y << 5) + la];
                #pragma unroll
                for (int d = 0; d < 16; d++)
                    hyr[d] = adjy*sw0[wrp*16 + d] + sb0[wrp*16 + d];
            } else {
                __pipeline_wait_prior(0);
                GBAR();                        // slab ready; prior buffer free
                float* cur = (i & 1) ? bufA : bufB;
                #pragma unroll
                for (int j = 0; j < 4; j++) {
                    float4 v = *(const float4*)&cur[la*68 + wrp*16 + 4*j];
                    hyr[4*j] = v.x; hyr[4*j+1] = v.y; hyr[4*j+2] = v.z; hyr[4*j+3] = v.w;
                }
                if (i < 3) {
                    float* nxt = (i & 1) ? bufB : bufA;
                    int yn = y + 2;
                    for (int v = tf; v < 512; v += 128)
                        __pipeline_memcpy_async(&nxt[(v >> 4)*68 + (v & 15)*4],
                                                hyb + (v >> 4)*2048 + yn*64 + (v & 15)*4, 16);
                    __pipeline_commit();
                }
            }

            // stats
            float s0 = 0.f, s1 = 0.f, dg = 0.f, mprod = 0.f, eprod = 0.f;
            #pragma unroll
            for (int d = 0; d < 16; d++) {
                s0 += hyr[d];
                s1 += hyr[d]*hyr[d];
                dg += gq[d]*hyr[d];
                float pr = hxr[d]*hyr[d];
                mprod += pr;
                eprod += pr*pr;
            }
            float mny = s0 * (1.f/16.f);
            float rsy = rsqrtf(s1*(1.f/16.f) - mny*mny + EPSL);
            float s = (rsy*(dg - mny*A) + Bc) * 0.25f;
            float mm = mprod * (1.f/16.f);
            float rstd = rsqrtf(eprod*(1.f/16.f) - mm*mm + EPSL);

            // deferred-normalization softmax
            float ex = __expf(s);
            float wpr = ex * rstd;
            #pragma unroll
            for (int j = 0; j < 4; j++) {
                float4 v;
                v.x = wpr*hxr[4*j  ]*hyr[4*j  ];
                v.y = wpr*hxr[4*j+1]*hyr[4*j+1];
                v.z = wpr*hxr[4*j+2]*hyr[4*j+2];
                v.w = wpr*hxr[4*j+3]*hyr[4*j+3];
                *(float4*)&ctw[la*20 + 4*j] = v;
            }
            float t2 = ex, t3 = ex * mm * rstd;
            #pragma unroll
            for (int o = 16; o > 0; o >>= 1) {
                t2 += __shfl_xor_sync(~0u, t2, o);
                t3 += __shfl_xor_sync(~0u, t3, o);
            }
            __syncwarp();
            {
                int dd = la & 15, hh = la >> 4;
                float a0 = 0.f, a1 = 0.f, a2 = 0.f, a3 = 0.f;
                #pragma unroll
                for (int aa = 0; aa < 4; aa++) {
                    a0 += ctw[((aa     )*2 + hh)*20 + dd];
                    a1 += ctw[((aa +  4)*2 + hh)*20 + dd];
                    a2 += ctw[((aa +  8)*2 + hh)*20 + dd];
                    a3 += ctw[((aa + 12)*2 + hh)*20 + dd];
                }
                float acc = (a0 + a1) + (a2 + a3);
                acc += __shfl_xor_sync(~0u, acc, 16);
                if (la < 16) {
                    float xuv = (acc - t3) * (1.f / t2);
                    sxup[i*64 + wrp*16 + la] = slg[la]*xuv + slb[la];
                }
            }
            __syncwarp();                      // ctw safe for next iter
        } // y loop

        GBAR();                                // all sxup[*] visible to group

        // ================= batched FFN over 4 cells =================
        float acc0, acc1, acc2, acc3;
        if (l == 0 && half == 0) {
            float w0f = sfw0[ffn_f];
            acc0 = fbias + w0f*sxo[0];
            acc1 = fbias + w0f*sxo[64];
            acc2 = fbias + w0f*sxo[128];
            acc3 = fbias + w0f*sxo[192];
        } else {
            const float4* fw = (const float4*)&dyn[OFF_FW + ffn_f*140 + (half ? 68 : 0)];
            float base = half ? 0.f : fbias;
            acc0 = base; acc1 = base; acc2 = base; acc3 = base;
            const float4* x0 = (const float4*)(half ? (sxup)       : (sxo));
            const float4* x1 = (const float4*)(half ? (sxup + 64)  : (sxo + 64));
            const float4* x2 = (const float4*)(half ? (sxup + 128) : (sxo + 128));
            const float4* x3 = (const float4*)(half ? (sxup + 192) : (sxo + 192));
            #pragma unroll
            for (int j = 0; j < 16; j++) {
                float4 w = fw[j];
                float4 v0 = x0[j], v1 = x1[j], v2 = x2[j], v3 = x3[j];
                acc0 += w.x*v0.x + w.y*v0.y + w.z*v0.z + w.w*v0.w;
                acc1 += w.x*v1.x + w.y*v1.y + w.z*v1.z + w.w*v1.w;
                acc2 += w.x*v2.x + w.y*v2.y + w.z*v2.z + w.w*v2.w;
                acc3 += w.x*v3.x + w.y*v3.y + w.z*v3.z + w.w*v3.w;
            }
        }
        acc0 += __shfl_xor_sync(~0u, acc0, 1);
        acc1 += __shfl_xor_sync(~0u, acc1, 1);
        acc2 += __shfl_xor_sync(~0u, acc2, 1);
        acc3 += __shfl_xor_sync(~0u, acc3, 1);

        // LN trees for 4 cells (pipelined)
        {
            float u0 = acc0, u1 = acc1, u2 = acc2, u3 = acc3;
            float q0 = acc0*acc0, q1 = acc1*acc1, q2 = acc2*acc2, q3 = acc3*acc3;
            #pragma unroll
            for (int o = 16; o > 0; o >>= 1) {
                u0 += __shfl_xor_sync(~0u, u0, o);
                u1 += __shfl_xor_sync(~0u, u1, o);
                u2 += __shfl_xor_sync(~0u, u2, o);
                u3 += __shfl_xor_sync(~0u, u3, o);
                q0 += __shfl_xor_sync(~0u, q0, o);
                q1 += __shfl_xor_sync(~0u, q1, o);
                q2 += __shfl_xor_sync(~0u, q2, o);
                q3 += __shfl_xor_sync(~0u, q3, o);
            }
            if (la == 0) {
                sred [ypar][0][wrp] = u0; sred [ypar][1][wrp] = u1;
                sred [ypar][2][wrp] = u2; sred [ypar][3][wrp] = u3;
                sred2[ypar][0][wrp] = q0; sred2[ypar][1][wrp] = q1;
                sred2[ypar][2][wrp] = q2; sred2[ypar][3][wrp] = q3;
            }
        }
        GBAR();

        // ---- prefetch NEXT layer's FFN weights (FW region dead now) ----
        if (l < LL - 1) {
            for (int i = t; i < 2048; i += TPB) {
                int f = i >> 5, u = i & 31;
                __pipeline_memcpy_async(&dyn[OFF_FW + f*140 + u*4 + (u >= 16 ? 4 : 0)],
                                        fWs + l*8192 + f*128 + u*4, 16);
            }
            __pipeline_commit();
        }

        // ---- epilogue: LN + write sxn + pooling, per cell ----
        float offm = -3.0e38f, minv = 3.0e38f, dval = -3.0e38f;
        bool sawdiag = false;
        float accs[4] = {acc0, acc1, acc2, acc3};
        #pragma unroll
        for (int c = 0; c < 4; c++) {
            float mean = (sred[ypar][c][0] + sred[ypar][c][1] +
                          sred[ypar][c][2] + sred[ypar][c][3]) * (1.f/128.f);
            float ms   = (sred2[ypar][c][0] + sred2[ypar][c][1] +
                          sred2[ypar][c][2] + sred2[ypar][c][3]) * (1.f/128.f);
            float xn = (accs[c] - mean)*rsqrtf(ms - mean*mean + EPSL)*flg + flb;
            int y = y0 + 2*c + ypar;
            if (half == 0) {
                if (l < LL - 1) sxn[c*64 + ffn_f] = xn;
                minv = fminf(minv, xn);
                if (y == x) { dval = xn; sawdiag = true; }
                else offm = fmaxf(offm, xn);
            }
        }

        // ---- pooling atomics ----
        if (half == 0) {
            atomicMax(&g_off_key[l*128 + b*64 + ffn_f], fkey(offm));
            if (sawdiag) atomicMax(&g_diag_key[l*128 + b*64 + ffn_f], fkey(dval));
        }
        {
            float w = minv;
            #pragma unroll
            for (int o = 16; o > 0; o >>= 1) w = fminf(w, __shfl_xor_sync(~0u, w, o));
            if (la == 0) atomicMin(&g_min_key4[l], fkey(w));
        }

        // ---- prefetch h-tail W (l>=1) into ADJ region ----
        if (l >= 1 && l < LL - 1) {
            for (int v = tf; v < 512; v += 128) {
                int f = ypar*32 + (v >> 4), u = v & 15;
                __pipeline_memcpy_async(&dyn[OFF_ADJ + f*68 + u*4],
                                        Ws + l*4096 + f*64 + u*4, 16);
            }
            __pipeline_commit();
        }

        // ---- h-tail: next-layer h for own 8 cells ----
        if (l < LL - 1) {
            __pipeline_wait_prior(0);          // FW(l+1) + Wtail
            __syncthreads();
            const float* wbase = (l == 0) ? (dyn + OFF_SY) : (dyn + OFF_ADJ);
            int f = t & 63, yyA = t >> 6, yyB = yyA + 4;
            const float4* wrow = (const float4*)&wbase[f*68];
            const float4* xA = (const float4*)&dyn[OFF_XA + ((l+1)&1)*512 + (yyA & 1)*256 + (yyA >> 1)*64];
            const float4* xB = (const float4*)&dyn[OFF_XA + ((l+1)&1)*512 + (yyB & 1)*256 + (yyB >> 1)*64];
            float accA = bs[l*64 + f], accB = accA;
            #pragma unroll
            for (int j = 0; j < 16; j++) {
                float4 w = wrow[j], va = xA[j], vb = xB[j];
                accA += w.x*va.x + w.y*va.y + w.z*va.z + w.w*va.w;
                accB += w.x*vb.x + w.y*vb.y + w.z*vb.z + w.w*vb.w;
            }
            float* hn = g_hbuf[(l+1) & 1];
            hn[((b*32 + x)*32 + y0 + yyA)*64 + f] = accA;
            hn[((b*32 + x)*32 + y0 + yyB)*64 + f] = accB;
            gsync_b(b);                        // per-batch barrier
        }
    } // layers

    // ================= final: arrive-only barrier + block 0 finishes =================
    __syncthreads();
    if (blk != 0) {
        if (t == 0) { __threadfence(); atomicAdd(&g_fin, 1); }
        return;
    }
    if (t == 0) {
        while (*(volatile int*)&g_fin != GRID - 1) {}
        g_fin = 0;
        __threadfence();
    }
    __syncthreads();
    {
        float* pooled4 = dyn + OFF_CT;         // 4 x 256
        float* psum    = dyn + OFF_FW;         // 256
        for (int l2 = 0; l2 < LL; l2++) {
            float d0 = 0.f, d1 = 0.f, o0 = 0.f, o1 = 0.f, gmin = 0.f;
            if (t < 64) {
                d0 = funkey(g_diag_key[l2*128 + t]);
                d1 = funkey(g_diag_key[l2*128 + 64 + t]);
                o0 = funkey(g_off_key [l2*128 + t]);
                o1 = funkey(g_off_key [l2*128 + 64 + t]);
                gmin = funkey(g_min_key4[l2]);
                float m = fmaxf(d0, d1);
                #pragma unroll
                for (int o = 16; o > 0; o >>= 1) m = fmaxf(m, __shfl_xor_sync(~0u, m, o));
                if ((t & 31) == 0) psr[t >> 5] = m;
            }
            __syncthreads();
            if (t < 64) {
                float gdm = fmaxf(psr[0], psr[1]);
                float val = fabsf(gdm - gmin);
                pooled4[l2*256 + t]       = d0;
                pooled4[l2*256 + 64 + t]  = fmaxf(o0, d0 - val);
                pooled4[l2*256 + 128 + t] = d1;
                pooled4[l2*256 + 192 + t] = fmaxf(o1, d1 - val);
            }
            __syncthreads();
        }
        {
            int l2 = t >> 6, bq = (t >> 5) & 1, j = t & 31;
            const float4* w4 = (const float4*)(opW + l2*4096 + j*128);
            const float4* p4 = (const float4*)&pooled4[l2*256 + bq*128];
            float acc = opb[l2*32 + j];
            #pragma unroll
            for (int k = 0; k < 32; k++) {
                float4 w = w4[k], p = p4[k];
                acc += w.x*p.x + w.y*p.y + w.z*p.z + w.w*p.w;
            }
            psum[t] = acc;
        }
        __syncthreads();
        if (t < 32) {
            float s0 = psum[t]      + psum[64 + t] + psum[128 + t] + psum[192 + t];
            float s1 = psum[32 + t] + psum[96 + t] + psum[160 + t] + psum[224 + t];
            float m = 0.5f*(s0 + s1);
            float v = 0.5f*((s0 - m)*(s0 - m) + (s1 - m)*(s1 - m));
            float r = rsqrtf(v + EPSL);
            out[t]      = (s0 - m)*r;
            out[32 + t] = (s1 - m)*r;
        }
        // reset keys for next graph replay
        __syncthreads();
        for (int i = t; i < LL*128; i += TPB) { g_diag_key[i] = 0u; g_off_key[i] = 0u; }
        if (t < LL) g_min_key4[t] = 0xFFFFFFFFu;
    }
}

// ---------------- launch ----------------
extern "C" void kernel_launch(void* const* d_in, const int* in_sizes, int n_in,
                              void* d_out, int out_size) {
    const int*   ei    = (const int*)  d_in[0];
    const float* W0    = (const float*)d_in[2];
    const float* b0    = (const float*)d_in[3];
    const float* Ws    = (const float*)d_in[4];
    const float* bs    = (const float*)d_in[5];
    const float* ln_g  = (const float*)d_in[6];
    const float* ln_b  = (const float*)d_in[7];
    const float* fW0   = (const float*)d_in[8];
    const float* fb0   = (const float*)d_in[9];
    const float* fWs   = (const float*)d_in[10];
    const float* fbs   = (const float*)d_in[11];
    const float* fln_g = (const float*)d_in[12];
    const float* fln_b = (const float*)d_in[13];
    const float* opW   = (const float*)d_in[14];
    const float* opb   = (const float*)d_in[15];
    int E = in_sizes[0] / 2;

    cudaFuncSetAttribute(mega, cudaFuncAttributeMaxDynamicSharedMemorySize, DYNB);
    mega<<<GRID, TPB, DYNB>>>(ei, E, W0, b0, Ws, bs, ln_g, ln_b,
                              fW0, fb0, fWs, fbs, fln_g, fln_b,
                              opW, opb, (float*)d_out);
}